// round 6
// baseline (speedup 1.0000x reference)
#include <cuda_runtime.h>
#include <math.h>

#define B_ 4096
#define T_ 256
#define V_ 16
#define E_ 10
#define H_ 50
#define O_ 16

#define BLOCK_ 512
#define ROWS_PER_BLOCK_ (BLOCK_ / O_)        // 32
#define GRID_ (B_ / ROWS_PER_BLOCK_)         // 128 -> single wave on 148 SMs

// sigmoid / tanh via MUFU (EX2 + RCP): ~1e-6 rel error, well under 1e-3 budget.
__device__ __forceinline__ float fast_sigmoid(float x) {
    return __fdividef(1.0f, 1.0f + __expf(-x));
}
__device__ __forceinline__ float fast_tanh(float x) {
    return fmaf(2.0f, __fdividef(1.0f, 1.0f + __expf(-2.0f * x)), -1.0f);
}

__device__ __forceinline__ void copy_f4(float* dst, const float* src, int n,
                                        int tid, int nthreads) {
    const float4* s = reinterpret_cast<const float4*>(src);
    float4* d = reinterpret_cast<float4*>(dst);
    for (int i = tid; i < (n >> 2); i += nthreads) d[i] = s[i];
}

// Only x[b, T-1] matters; output depends solely on the token value in [0,16).
// Single-wave version: 128 blocks x 512 threads, 32 rows/block, one output
// float per thread. Each thread pre-loads its w_out row into REGISTERS before
// the barrier (overlapped with w1 smem staging + phase 1), so phase 2 is a
// dual-accumulator FMA-from-register chain fed by broadcast LDS.
__global__ __launch_bounds__(BLOCK_, 1)
void dclstm_kernel(const int* __restrict__ x,
                   const float* __restrict__ emb,
                   const float* __restrict__ w1,
                   const float* __restrict__ b1,
                   const float* __restrict__ b2,
                   const float* __restrict__ w_out,
                   const float* __restrict__ b_out,
                   float* __restrict__ out)
{
    __shared__ float s_w1[4 * H_ * E_];   // 2000
    __shared__ float s_b12[4 * H_];       // 200 (b1+b2 fused)
    __shared__ float s_emb[V_ * E_];      // 160
    __shared__ float sh_h[V_][H_];        // 16 x 50

    const int tid = threadIdx.x;
    const int k   = tid & 15;             // output channel 0..15
    const int local_row = tid >> 4;       // 0..31
    const int row = blockIdx.x * ROWS_PER_BLOCK_ + local_row;

    // --- Independent global loads, all issued up front (max MLP) ---
    // 1) token for this thread's row (16 threads broadcast per row)
    const int tok = x[row * T_ + (T_ - 1)];

    // 2) this thread's w_out row -> registers (50 floats; 16-thread broadcast)
    float wk[H_ + 2];                     // pad to 52 for float4 loads
    {
        // w_out rows are 50 floats (200B), not 16B aligned per row, so load
        // scalar pairs via float2 where possible: k*H_ is even*? k*50 is
        // always even -> 8B aligned. Use float2 (25 loads).
        const float2* src = reinterpret_cast<const float2*>(w_out + k * H_);
#pragma unroll
        for (int i = 0; i < H_ / 2; ++i) {
            float2 v = src[i];
            wk[2 * i]     = v.x;
            wk[2 * i + 1] = v.y;
        }
    }
    const float bk = b_out[k];

    // 3) stage w1 / emb / fused biases to smem (coalesced float4)
    copy_f4(s_w1,  w1,  4 * H_ * E_, tid, BLOCK_);
    copy_f4(s_emb, emb, V_ * E_,     tid, BLOCK_);
    {
        const float4* pb1 = reinterpret_cast<const float4*>(b1);
        const float4* pb2 = reinterpret_cast<const float4*>(b2);
        float4* d = reinterpret_cast<float4*>(s_b12);
        for (int i = tid; i < H_; i += BLOCK_) {   // 50 float4 chunks
            float4 a = pb1[i], b = pb2[i];
            d[i] = make_float4(a.x + b.x, a.y + b.y, a.z + b.z, a.w + b.w);
        }
    }
    __syncthreads();

    // ---- Phase 1: hidden states. 16 tokens x 32 lanes, <=2 units/thread ----
    {
        const int v    = tid >> 5;        // token 0..15
        const int lane = tid & 31;        // 0..31

        float xe[E_];
#pragma unroll
        for (int e = 0; e < E_; ++e) xe[e] = s_emb[v * E_ + e];

#pragma unroll
        for (int rep = 0; rep < 2; ++rep) {
            const int j = lane + rep * 32;
            if (j < H_) {
                float pi = s_b12[j];
                float po = s_b12[100 + j];
                float pg = s_b12[150 + j];
#pragma unroll
                for (int e = 0; e < E_; ++e) {
                    const float xev = xe[e];
                    pi = fmaf(s_w1[(j)       * E_ + e], xev, pi);
                    po = fmaf(s_w1[(100 + j) * E_ + e], xev, po);
                    pg = fmaf(s_w1[(150 + j) * E_ + e], xev, pg);
                }
                const float it = fast_sigmoid(pi);
                const float ot = fast_sigmoid(po);
                const float g  = fast_tanh(pg);
                sh_h[v][j] = ot * fast_tanh(it * g);
            }
        }
    }
    __syncthreads();

    // ---- Phase 2: one output/thread, w_out in regs, dual accumulators ----
    float s0 = bk, s1 = 0.0f;
#pragma unroll
    for (int j = 0; j < H_; j += 2) {
        s0 = fmaf(sh_h[tok][j],     wk[j],     s0);
        s1 = fmaf(sh_h[tok][j + 1], wk[j + 1], s1);
    }
    out[blockIdx.x * BLOCK_ + tid] = s0 + s1;   // == out[row*O_ + k]
}

extern "C" void kernel_launch(void* const* d_in, const int* in_sizes, int n_in,
                              void* d_out, int out_size)
{
    // metadata order: x, emb, w1, b1, w2, b2, w_out, b_out
    const int*   x     = (const int*)  d_in[0];
    const float* emb   = (const float*)d_in[1];
    const float* w1    = (const float*)d_in[2];
    const float* b1    = (const float*)d_in[3];
    // d_in[4] = w2 (unused by the reference)
    const float* b2    = (const float*)d_in[5];
    const float* w_out = (const float*)d_in[6];
    const float* b_out = (const float*)d_in[7];
    float* out = (float*)d_out;

    dclstm_kernel<<<GRID_, BLOCK_>>>(x, emb, w1, b1, b2, w_out, b_out, out);
}

// round 7
// speedup vs baseline: 1.0036x; 1.0036x over previous
#include <cuda_runtime.h>
#include <math.h>

#define B_ 4096
#define T_ 256
#define V_ 16
#define E_ 10
#define H_ 50
#define O_ 16

#define BLOCK_ 512
#define ROWS_PER_BLOCK_ (BLOCK_ / O_)        // 32
#define GRID_ (B_ / ROWS_PER_BLOCK_)         // 128 -> single wave

// sigmoid / tanh via MUFU (EX2 + RCP): ~1e-6 rel error, well under 1e-3 budget.
__device__ __forceinline__ float fast_sigmoid(float x) {
    return __fdividef(1.0f, 1.0f + __expf(-x));
}
__device__ __forceinline__ float fast_tanh(float x) {
    return fmaf(2.0f, __fdividef(1.0f, 1.0f + __expf(-2.0f * x)), -1.0f);
}

// Only x[b, T-1] matters; output depends solely on the token value in [0,16).
// Minimal-critical-path version: NO param smem staging (all params are L2-hot
// across graph replays; L1 is flushed per launch anyway). Phase 1 computes the
// 16x50 hidden matrix straight from global into smem; phase 2 is one output
// float per thread from registers + broadcast LDS. Exactly one __syncthreads.
__global__ __launch_bounds__(BLOCK_, 1)
void dclstm_kernel(const int* __restrict__ x,
                   const float* __restrict__ emb,
                   const float* __restrict__ w1,
                   const float* __restrict__ b1,
                   const float* __restrict__ b2,
                   const float* __restrict__ w_out,
                   const float* __restrict__ b_out,
                   float* __restrict__ out)
{
    __shared__ float sh_h[V_][H_];        // 16 x 50

    const int tid = threadIdx.x;
    const int k   = tid & 15;             // output channel 0..15
    const int row = blockIdx.x * ROWS_PER_BLOCK_ + (tid >> 4);

    // ---- Independent global loads issued up front (max MLP, all L2-hot) ----
    const int tok = x[row * T_ + (T_ - 1)];           // token for my row

    float wk[H_];                                      // my w_out row (50)
    {
        const float2* src = reinterpret_cast<const float2*>(w_out + k * H_);
#pragma unroll
        for (int i = 0; i < H_ / 2; ++i) {             // k*50 floats -> 8B aligned
            float2 v = src[i];
            wk[2 * i]     = v.x;
            wk[2 * i + 1] = v.y;
        }
    }
    const float bk = b_out[k];

    // ---- Phase 1: hidden states. 16 tokens x 32 lanes, <=2 units/thread ----
    {
        const int v    = tid >> 5;        // token 0..15
        const int lane = tid & 31;        // 0..31

        float xe[E_];
#pragma unroll
        for (int e = 0; e < E_; ++e) xe[e] = emb[v * E_ + e];   // broadcast L2

#pragma unroll
        for (int rep = 0; rep < 2; ++rep) {
            const int j = lane + rep * 32;
            if (j < H_) {
                float pi = b1[j]       + b2[j];
                float po = b1[100 + j] + b2[100 + j];
                float pg = b1[150 + j] + b2[150 + j];
#pragma unroll
                for (int e = 0; e < E_; ++e) {
                    const float xev = xe[e];
                    pi = fmaf(w1[(j)       * E_ + e], xev, pi);
                    po = fmaf(w1[(100 + j) * E_ + e], xev, po);
                    pg = fmaf(w1[(150 + j) * E_ + e], xev, pg);
                }
                const float it = fast_sigmoid(pi);
                const float ot = fast_sigmoid(po);
                const float g  = fast_tanh(pg);
                sh_h[v][j] = ot * fast_tanh(it * g);
            }
        }
    }
    __syncthreads();

    // ---- Phase 2: one output/thread, w_out in regs, dual accumulators ----
    float s0 = bk, s1 = 0.0f;
#pragma unroll
    for (int j = 0; j < H_; j += 2) {
        s0 = fmaf(sh_h[tok][j],     wk[j],     s0);
        s1 = fmaf(sh_h[tok][j + 1], wk[j + 1], s1);
    }
    out[blockIdx.x * BLOCK_ + tid] = s0 + s1;   // == out[row*O_ + k], coalesced
}

extern "C" void kernel_launch(void* const* d_in, const int* in_sizes, int n_in,
                              void* d_out, int out_size)
{
    // metadata order: x, emb, w1, b1, w2, b2, w_out, b_out
    const int*   x     = (const int*)  d_in[0];
    const float* emb   = (const float*)d_in[1];
    const float* w1    = (const float*)d_in[2];
    const float* b1    = (const float*)d_in[3];
    // d_in[4] = w2 (unused by the reference)
    const float* b2    = (const float*)d_in[5];
    const float* w_out = (const float*)d_in[6];
    const float* b_out = (const float*)d_in[7];
    float* out = (float*)d_out;

    dclstm_kernel<<<GRID_, BLOCK_>>>(x, emb, w1, b1, b2, w_out, b_out, out);
}